// round 15
// baseline (speedup 1.0000x reference)
#include <cuda_runtime.h>

#define NG   512
#define S    128
#define FENC 16777216.0          // 2^24 fixed-point encode grain
#define FDEC 8388608.0           // 2^23 decode: /2 gap applies pair-symmetry x2
#define CNT_BIT 54
#define SUM_MASK ((1ULL << CNT_BIT) - 1ULL)

__device__ unsigned long long g_acc = 0ULL;   // bits[0,54): fx sum, bits[54+): count

// 512 CTAs x 512 threads (CTA = one group, 4 CTAs/SM = HW max threads).
// i-REGISTER-BLOCKING: thread (rp = t&63, q = t>>6) owns rows e=2rp, o=2rp+1
// and d-octave D = [8q+1, 8q+8]. It loads j = e+8q+1+k for k=0..8 (NINE
// shared-j loads serving SIXTEEN pairs):
//   e-pair at k=0..7  (d = 8q+1+k), o-pair at k=1..8 (d = 8q+k).
// This cuts SMEM crossbar bytes per pair ~45% — the measured plateau's
// dominant floor (64 warps x 16 iters x 6 cyc ~ 6.1K cyc/SM before).
// Rows 0..63 duplicated at 128..191 implement the cyclic wrap, so the
// cyclic-distance decomposition covers each unordered pair exactly once;
// d=64 terms (q=7: e@k=7, o@k=8) weighted by rp<32.
// (sqrt a - sqrt b)^2 = a + b - 2*sqrt(ab) via sqrt.approx (sqrt(0)=0
// matches the grad-safe pdist).
// Gather/dtype/tail unchanged from r14 (proven): warps 0-7 gather with
// per-warp dtype ballot (odd dwords 129..191, <1KB safe both layouts),
// single packed {fx, count} relaxed atomicAdd tail, last CTA writes mean.
__global__ void __launch_bounds__(512, 4)
loss_kernel(const float* __restrict__ inputs,
            const float* __restrict__ target,
            const void*  __restrict__ positions,
            float* __restrict__ out) {
    __shared__ float4 A[S + 64];
    __shared__ float2 B[S + 64];
    __shared__ float  wsum[16];

    const int tid = threadIdx.x;
    const int g   = blockIdx.x;

    // ---- gather (warps 0-7): t<128 inputs row, 128<=t<256 target row ----
    if (tid < 2 * S) {
        const int grow = tid & (S - 1);
        const unsigned* pw = (const unsigned*)positions;
        const unsigned p32 = pw[g * S + grow];                // speculative
        const unsigned chk = pw[129 + 2 * (tid & 31)];        // <1KB, safe
        const unsigned any = __ballot_sync(0xffffffffu, chk != 0u);
        int p = (int)p32;
        if (any == 0u)                                        // int64 layout
            p = (int)((const long long*)positions)[g * S + grow];

        const float* src = (tid < S ? inputs : target) + (size_t)p * 9 + 3;
        const float x0 = src[0], x1 = src[1], x2 = src[2];
        if (tid < S) {
            A[grow].x = x0; A[grow].y = x1; A[grow].z = x2;
            if (grow < 64) { A[grow + S].x = x0; A[grow + S].y = x1; A[grow + S].z = x2; }
        } else {
            A[grow].w = x0;
            const float2 bv = make_float2(x1, x2);
            B[grow] = bv;
            if (grow < 64) { A[grow + S].w = x0; B[grow + S] = bv; }
        }
    }
    __syncthreads();

    // ---- register-blocked pair loop ----
    const int rp = tid & 63;           // row pair index
    const int q  = tid >> 6;           // d-octave 0..7
    const int e  = 2 * rp;             // even row
    const int j0 = e + 8 * q + 1;      // first j; k = 0..8

    const float4 ae = A[e];     const float2 be = B[e];
    const float4 ao = A[e + 1]; const float2 bo = B[e + 1];
    const float xe0 = ae.x, xe1 = ae.y, xe2 = ae.z;
    const float te0 = ae.w, te1 = be.x, te2 = be.y;
    const float xo0 = ao.x, xo1 = ao.y, xo2 = ao.z;
    const float to0 = ao.w, to1 = bo.x, to2 = bo.y;

    const float4* qa = &A[j0];
    const float2* qb = &B[j0];
    // d=64 appears only at q==7 (e-pair k=7, o-pair k=8); count iff rp<32
    const float wTop = (q == 7 && rp >= 32) ? 0.0f : 1.0f;

    float accA = 0.f, accB = 0.f, accSq = 0.f;
#pragma unroll
    for (int k = 0; k < 9; ++k) {
        const float4 va = qa[k];
        const float2 vb = qb[k];
        // ---- pair with even row (valid for k <= 7) ----
        if (k <= 7) {
            const float dx0 = va.x - xe0, dx1 = va.y - xe1, dx2 = va.z - xe2;
            const float a = dx0 * dx0 + dx1 * dx1 + dx2 * dx2;
            const float dt0 = va.w - te0, dt1 = vb.x - te1, dt2 = vb.y - te2;
            const float b = dt0 * dt0 + dt1 * dt1 + dt2 * dt2;
            float sq;
            asm("sqrt.approx.f32 %0, %1;" : "=f"(sq) : "f"(a * b));
            if (k == 7) {      // d = 8q+8: only q==7 hits d=64
                accA = fmaf(wTop, a,  accA);
                accB = fmaf(wTop, b,  accB);
                accSq = fmaf(wTop, sq, accSq);
            } else {
                accA += a; accB += b; accSq += sq;
            }
        }
        // ---- pair with odd row (valid for k >= 1) ----
        if (k >= 1) {
            const float dx0 = va.x - xo0, dx1 = va.y - xo1, dx2 = va.z - xo2;
            const float a = dx0 * dx0 + dx1 * dx1 + dx2 * dx2;
            const float dt0 = va.w - to0, dt1 = vb.x - to1, dt2 = vb.y - to2;
            const float b = dt0 * dt0 + dt1 * dt1 + dt2 * dt2;
            float sq;
            asm("sqrt.approx.f32 %0, %1;" : "=f"(sq) : "f"(a * b));
            if (k == 8) {      // d = 8q+8 for the odd row
                accA = fmaf(wTop, a,  accA);
                accB = fmaf(wTop, b,  accB);
                accSq = fmaf(wTop, sq, accSq);
            } else {
                accA += a; accB += b; accSq += sq;
            }
        }
    }
    float acc = (accA + accB) - 2.0f * accSq;

    // ---- block reduction (16 warps) ----
#pragma unroll
    for (int off = 16; off > 0; off >>= 1)
        acc += __shfl_xor_sync(0xffffffffu, acc, off);
    const int lane = tid & 31, warp = tid >> 5;
    if (lane == 0) wsum[warp] = acc;
    __syncthreads();

    // ---- single packed-atomic tail (tid 0 only) ----
    if (tid == 0) {
        float s = 0.0f;
#pragma unroll
        for (int w = 0; w < 16; ++w) s += wsum[w];
        s = fmaxf(s, 0.0f);                       // guard the count field
        const unsigned long long fx =
            (unsigned long long)(long long)((double)s * FENC);
        const unsigned long long add = fx + (1ULL << CNT_BIT);
        const unsigned long long old = atomicAdd(&g_acc, add);
        if ((old >> CNT_BIT) == (unsigned long long)(NG - 1)) {
            const unsigned long long tot = (old & SUM_MASK) + fx;
            out[0] = (float)((double)tot / FDEC / ((double)NG * S * S));
            g_acc = 0ULL;                          // reset for next replay
        }
    }
}

extern "C" void kernel_launch(void* const* d_in, const int* in_sizes, int n_in,
                              void* d_out, int out_size) {
    const float* inputs    = (const float*)d_in[0];
    const float* target    = (const float*)d_in[1];
    const void*  positions = d_in[2];
    loss_kernel<<<NG, 512>>>(inputs, target, positions, (float*)d_out);
}